// round 4
// baseline (speedup 1.0000x reference)
#include <cuda_runtime.h>
#include <cuda_bf16.h>
#include <cstdint>

namespace {

constexpr int Bn = 2, Hn = 16, SQn = 2048, SKn = 2048, Dn = 128;
constexpr int STRIDE_W = 68;             // 32-bit words per padded smem row (128 bf16 + 8 pad)
constexpr int STRIDE_B = STRIDE_W * 4;   // 272 bytes
constexpr int TILE_W   = 128 * STRIDE_W; // words per tile buffer (34816 B)
constexpr int TILE_B   = TILE_W * 4;
constexpr float SCALE  = 22.62741699796952f; // 2 * sqrt(128)

__device__ __forceinline__ uint32_t packbf(float a, float b) {
    __nv_bfloat162 t = __floats2bfloat162_rn(a, b);
    return *reinterpret_cast<uint32_t*>(&t);
}
__device__ __forceinline__ uint32_t prmt_hi(uint32_t a, uint32_t b) {
    uint32_t d;
    asm("prmt.b32 %0,%1,%2,0x7632;" : "=r"(d) : "r"(a), "r"(b));
    return d;
}
__device__ __forceinline__ void mma16816(float* d, const uint32_t* a, uint32_t b0, uint32_t b1) {
    asm volatile(
        "mma.sync.aligned.m16n8k16.row.col.f32.bf16.bf16.f32 "
        "{%0,%1,%2,%3}, {%4,%5,%6,%7}, {%8,%9}, {%0,%1,%2,%3};\n"
        : "+f"(d[0]), "+f"(d[1]), "+f"(d[2]), "+f"(d[3])
        : "r"(a[0]), "r"(a[1]), "r"(a[2]), "r"(a[3]), "r"(b0), "r"(b1));
}
__device__ __forceinline__ void ldsm4(uint32_t* r, uint32_t saddr) {
    asm volatile("ldmatrix.sync.aligned.m8n8.x4.shared.b16 {%0,%1,%2,%3}, [%4];\n"
                 : "=r"(r[0]), "=r"(r[1]), "=r"(r[2]), "=r"(r[3]) : "r"(saddr));
}
__device__ __forceinline__ void ldsm4t(uint32_t* r, uint32_t saddr) {
    asm volatile("ldmatrix.sync.aligned.m8n8.x4.trans.shared.b16 {%0,%1,%2,%3}, [%4];\n"
                 : "=r"(r[0]), "=r"(r[1]), "=r"(r[2]), "=r"(r[3]) : "r"(saddr));
}

// fp32 -> (hi=trunc-bf16, lo=rn-bf16 of remainder) split, row-major padded tile
__device__ __forceinline__ void cvt_store_tile(uint32_t* H, uint32_t* L,
                                               const float4* __restrict__ src, int tid) {
    #pragma unroll
    for (int it = 0; it < 16; ++it) {
        int idx = tid + it * 256;            // 0..4095 float4s
        int row = idx >> 5, c4 = idx & 31;
        float4 v = src[idx];
        uint32_t bx = __float_as_uint(v.x), by = __float_as_uint(v.y);
        uint32_t bz = __float_as_uint(v.z), bw = __float_as_uint(v.w);
        uint32_t h0 = prmt_hi(bx, by);
        uint32_t h1 = prmt_hi(bz, bw);
        float lx = v.x - __uint_as_float(bx & 0xFFFF0000u);
        float ly = v.y - __uint_as_float(by & 0xFFFF0000u);
        float lz = v.z - __uint_as_float(bz & 0xFFFF0000u);
        float lw = v.w - __uint_as_float(bw & 0xFFFF0000u);
        int off = row * STRIDE_W + c4 * 2;
        *reinterpret_cast<uint2*>(H + off) = make_uint2(h0, h1);
        *reinterpret_cast<uint2*>(L + off) = make_uint2(packbf(lx, ly), packbf(lz, lw));
    }
}

__global__ __launch_bounds__(256, 1) void attn_kernel(
    const float* __restrict__ Q, const float* __restrict__ K,
    const float* __restrict__ V, const int* __restrict__ M,
    float* __restrict__ O)
{
    extern __shared__ uint32_t smem[];
    uint32_t* Qh = smem;
    uint32_t* Ql = Qh + TILE_W;
    uint32_t* Kh = Ql + TILE_W;
    uint32_t* Kl = Kh + TILE_W;
    uint32_t* Vh = Kl + TILE_W;
    uint32_t* Vl = Vh + TILE_W;

    const uint32_t sbase = (uint32_t)__cvta_generic_to_shared(smem);
    const uint32_t sQh = sbase;
    const uint32_t sQl = sQh + TILE_B;
    const uint32_t sKh = sQl + TILE_B;
    const uint32_t sKl = sKh + TILE_B;
    const uint32_t sVh = sKl + TILE_B;
    const uint32_t sVl = sVh + TILE_B;

    const int tid  = threadIdx.x;
    const int warp = tid >> 5, lane = tid & 31;
    const int gid  = lane >> 2, qid = lane & 3;
    const int qr   = warp * 16;

    const size_t bh = blockIdx.y;
    const int    qt = blockIdx.x;

    const float* Qg = Q + (bh * SQn + (size_t)qt * 128) * Dn;
    const int*   Mg = M + (bh * SQn + (size_t)qt * 128) * SKn;
    float*       Og = O + (bh * SQn + (size_t)qt * 128) * Dn;

    // lane-derived ldmatrix address offsets (bytes)
    const uint32_t bkOff = ((lane & 7) + ((lane >> 4) & 1) * 8) * STRIDE_B + ((lane >> 3) & 1) * 16;
    const uint32_t vOff  = ((lane & 7) + ((lane >> 3) & 1) * 8) * STRIDE_B + ((lane >> 4) & 1) * 16;
    const uint32_t qOff  = (qr + (lane & 15)) * STRIDE_B + ((lane >> 4) & 1) * 16;

    // ---- Q tile: global -> smem (hi/lo) ----
    cvt_store_tile(Qh, Ql, reinterpret_cast<const float4*>(Qg), tid);
    __syncthreads();

    // ---- hoist Q fragments into registers (invariant across all K tiles) ----
    uint32_t qfh[8][4], qfl[8][4];
    #pragma unroll
    for (int ds = 0; ds < 8; ++ds) {
        ldsm4(qfh[ds], sQh + qOff + ds * 32);
        ldsm4(qfl[ds], sQl + qOff + ds * 32);
    }

    float o[16][4];
    #pragma unroll
    for (int i = 0; i < 16; ++i) {
        #pragma unroll
        for (int j = 0; j < 4; ++j) o[i][j] = 0.f;
    }

    #pragma unroll 1
    for (int kt = 0; kt < 16; ++kt) {
        __syncthreads();  // previous iteration's smem reads done
        cvt_store_tile(Kh, Kl, reinterpret_cast<const float4*>(K + (bh * SKn + (size_t)kt * 128) * Dn), tid);
        cvt_store_tile(Vh, Vl, reinterpret_cast<const float4*>(V + (bh * SKn + (size_t)kt * 128) * Dn), tid);
        __syncthreads();

        const int koff = kt * 128;
        #pragma unroll 1
        for (int nc = 0; nc < 4; ++nc) {       // 32-key chunks
            const int kb = nc * 32;

            // prefetch mask ints for this chunk
            const int* m0 = Mg + (size_t)(qr + gid) * SKn + koff + kb + qid * 2;
            const int* m1 = m0 + 8 * (size_t)SKn;
            int2 ma[4], mb[4];
            #pragma unroll
            for (int j = 0; j < 4; ++j) {
                ma[j] = *reinterpret_cast<const int2*>(m0 + j * 8);
                mb[j] = *reinterpret_cast<const int2*>(m1 + j * 8);
            }

            // ---- GEMM1: S[16q x 32k] = Q * K^T (bf16x3 split) ----
            float s[4][4];
            #pragma unroll
            for (int j = 0; j < 4; ++j) { s[j][0]=0.f; s[j][1]=0.f; s[j][2]=0.f; s[j][3]=0.f; }

            #pragma unroll
            for (int ds = 0; ds < 8; ++ds) {
                uint32_t bh0[4], bh1[4], bl0[4], bl1[4];
                const uint32_t kcol = bkOff + ds * 32;
                ldsm4(bh0, sKh + (uint32_t)(kb      ) * STRIDE_B + kcol);
                ldsm4(bh1, sKh + (uint32_t)(kb + 16) * STRIDE_B + kcol);
                ldsm4(bl0, sKl + (uint32_t)(kb      ) * STRIDE_B + kcol);
                ldsm4(bl1, sKl + (uint32_t)(kb + 16) * STRIDE_B + kcol);
                mma16816(s[0], qfh[ds], bh0[0], bh0[1]);
                mma16816(s[1], qfh[ds], bh0[2], bh0[3]);
                mma16816(s[2], qfh[ds], bh1[0], bh1[1]);
                mma16816(s[3], qfh[ds], bh1[2], bh1[3]);
                mma16816(s[0], qfl[ds], bh0[0], bh0[1]);
                mma16816(s[1], qfl[ds], bh0[2], bh0[3]);
                mma16816(s[2], qfl[ds], bh1[0], bh1[1]);
                mma16816(s[3], qfl[ds], bh1[2], bh1[3]);
                mma16816(s[0], qfh[ds], bl0[0], bl0[1]);
                mma16816(s[1], qfh[ds], bl0[2], bl0[3]);
                mma16816(s[2], qfh[ds], bl1[0], bl1[1]);
                mma16816(s[3], qfh[ds], bl1[2], bl1[3]);
            }

            // ---- mask + scale -> P (registers only) ----
            float p[4][4];
            #pragma unroll
            for (int j = 0; j < 4; ++j) {
                p[j][0] = ma[j].x ? s[j][0] * SCALE : 0.f;
                p[j][1] = ma[j].y ? s[j][1] * SCALE : 0.f;
                p[j][2] = mb[j].x ? s[j][2] * SCALE : 0.f;
                p[j][3] = mb[j].y ? s[j][3] * SCALE : 0.f;
            }

            // ---- GEMM2: O[16q x 128d] += P[16 x 32] * V[32 x 128] ----
            #pragma unroll
            for (int kk = 0; kk < 2; ++kk) {
                uint32_t ahi[4], alo[4];
                {
                    const float* p0 = p[kk*2 + 0];
                    const float* p1 = p[kk*2 + 1];
                    uint32_t b00=__float_as_uint(p0[0]), b01=__float_as_uint(p0[1]);
                    uint32_t b02=__float_as_uint(p0[2]), b03=__float_as_uint(p0[3]);
                    uint32_t b10=__float_as_uint(p1[0]), b11=__float_as_uint(p1[1]);
                    uint32_t b12=__float_as_uint(p1[2]), b13=__float_as_uint(p1[3]);
                    ahi[0] = prmt_hi(b00, b01);
                    ahi[1] = prmt_hi(b02, b03);
                    ahi[2] = prmt_hi(b10, b11);
                    ahi[3] = prmt_hi(b12, b13);
                    alo[0] = packbf(p0[0] - __uint_as_float(b00 & 0xFFFF0000u),
                                    p0[1] - __uint_as_float(b01 & 0xFFFF0000u));
                    alo[1] = packbf(p0[2] - __uint_as_float(b02 & 0xFFFF0000u),
                                    p0[3] - __uint_as_float(b03 & 0xFFFF0000u));
                    alo[2] = packbf(p1[0] - __uint_as_float(b10 & 0xFFFF0000u),
                                    p1[1] - __uint_as_float(b11 & 0xFFFF0000u));
                    alo[3] = packbf(p1[2] - __uint_as_float(b12 & 0xFFFF0000u),
                                    p1[3] - __uint_as_float(b13 & 0xFFFF0000u));
                }
                const uint32_t vbase = (uint32_t)(kb + kk * 16) * STRIDE_B + vOff;
                #pragma unroll
                for (int t = 0; t < 8; ++t) {
                    uint32_t vh[4], vl[4];
                    ldsm4t(vh, sVh + vbase + t * 32);
                    ldsm4t(vl, sVl + vbase + t * 32);
                    mma16816(o[2*t    ], ahi, vh[0], vh[1]);
                    mma16816(o[2*t + 1], ahi, vh[2], vh[3]);
                    mma16816(o[2*t    ], alo, vh[0], vh[1]);
                    mma16816(o[2*t + 1], alo, vh[2], vh[3]);
                    mma16816(o[2*t    ], ahi, vl[0], vl[1]);
                    mma16816(o[2*t + 1], ahi, vl[2], vl[3]);
                }
            }
        }
    }

    // ---- epilogue: write O (fp32) ----
    float* o0 = Og + (size_t)(qr + gid) * Dn + qid * 2;
    float* o1 = o0 + 8 * Dn;
    #pragma unroll
    for (int nd = 0; nd < 16; ++nd) {
        *reinterpret_cast<float2*>(o0 + nd * 8) = make_float2(o[nd][0], o[nd][1]);
        *reinterpret_cast<float2*>(o1 + nd * 8) = make_float2(o[nd][2], o[nd][3]);
    }
}

} // namespace

extern "C" void kernel_launch(void* const* d_in, const int* in_sizes, int n_in,
                              void* d_out, int out_size) {
    (void)in_sizes; (void)n_in; (void)out_size;
    const float* Q = (const float*)d_in[0];
    const float* K = (const float*)d_in[1];
    const float* V = (const float*)d_in[2];
    const int*   M = (const int*)d_in[3];
    float*       O = (float*)d_out;

    const int smem_bytes = 6 * TILE_B;  // 208896 B
    cudaFuncSetAttribute(attn_kernel, cudaFuncAttributeMaxDynamicSharedMemorySize, smem_bytes);

    dim3 grid(SQn / 128, Bn * Hn);
    attn_kernel<<<grid, 256, smem_bytes>>>(Q, K, V, M, O);
}

// round 6
// speedup vs baseline: 1.0750x; 1.0750x over previous
#include <cuda_runtime.h>
#include <cuda_bf16.h>
#include <cstdint>

namespace {

constexpr int SQn = 2048, SKn = 2048, Dn = 128;
constexpr float SCALE = 22.62741699796952f; // 2*sqrt(128)

constexpr int STRIDE_W = 68;             // words per padded row (128 bf16 + 16B pad)
constexpr int STRIDE_B = STRIDE_W * 4;   // 272 B
constexpr int QTILE_B  = 128 * STRIDE_B; // 34816 B (one of Qh/Ql)
constexpr int CHUNK_ROWS = 64;
constexpr int BUF_B   = CHUNK_ROWS * STRIDE_B;  // 17408 B (one of Kh/Kl/Vh/Vl per chunk)
constexpr int STAGE_B = 4 * BUF_B;              // 69632 B per stage
constexpr int SM_STAGE0 = 2 * QTILE_B;          // after Qh,Ql
constexpr int SMEM_TOTAL = SM_STAGE0 + 2 * STAGE_B; // 208896 B
constexpr int NCHUNK = SKn / CHUNK_ROWS;        // 32

// scratch: [bh(32)][chunk(32)][buf: KH,KL,VH,VL][row(64) * 272B]
__device__ __align__(16) char g_scratch[32ull * NCHUNK * STAGE_B];

__device__ __forceinline__ uint32_t packbf(float a, float b) {
    __nv_bfloat162 t = __floats2bfloat162_rn(a, b);
    return *reinterpret_cast<uint32_t*>(&t);
}
__device__ __forceinline__ uint32_t prmt_hi(uint32_t a, uint32_t b) {
    uint32_t d; asm("prmt.b32 %0,%1,%2,0x7632;" : "=r"(d) : "r"(a), "r"(b)); return d;
}
__device__ __forceinline__ float truncbf(float x) {
    return __uint_as_float(__float_as_uint(x) & 0xFFFF0000u);
}
__device__ __forceinline__ void mma16816(float* d, const uint32_t* a, uint32_t b0, uint32_t b1) {
    asm volatile(
        "mma.sync.aligned.m16n8k16.row.col.f32.bf16.bf16.f32 "
        "{%0,%1,%2,%3}, {%4,%5,%6,%7}, {%8,%9}, {%0,%1,%2,%3};\n"
        : "+f"(d[0]), "+f"(d[1]), "+f"(d[2]), "+f"(d[3])
        : "r"(a[0]), "r"(a[1]), "r"(a[2]), "r"(a[3]), "r"(b0), "r"(b1));
}
__device__ __forceinline__ void ldsm4(uint32_t* r, uint32_t saddr) {
    asm volatile("ldmatrix.sync.aligned.m8n8.x4.shared.b16 {%0,%1,%2,%3}, [%4];\n"
                 : "=r"(r[0]), "=r"(r[1]), "=r"(r[2]), "=r"(r[3]) : "r"(saddr));
}
__device__ __forceinline__ void ldsm4t(uint32_t* r, uint32_t saddr) {
    asm volatile("ldmatrix.sync.aligned.m8n8.x4.trans.shared.b16 {%0,%1,%2,%3}, [%4];\n"
                 : "=r"(r[0]), "=r"(r[1]), "=r"(r[2]), "=r"(r[3]) : "r"(saddr));
}
__device__ __forceinline__ void cp16(uint32_t sdst, const void* gsrc) {
    asm volatile("cp.async.cg.shared.global [%0], [%1], 16;" :: "r"(sdst), "l"(gsrc) : "memory");
}
#define CP_COMMIT() asm volatile("cp.async.commit_group;" ::: "memory")
#define CP_WAIT(n)  asm volatile("cp.async.wait_group %0;" :: "n"(n) : "memory")

// ---------------- pre-pass: K,V fp32 -> hi/lo bf16 scratch ----------------
__global__ __launch_bounds__(256) void prepass(const float* __restrict__ K,
                                               const float* __restrict__ V) {
    uint32_t g = blockIdx.x * 256u + threadIdx.x;   // 0 .. 4194303
    int c4 = g & 31;                 // float4 within row
    int r  = (g >> 5) & 2047;        // key row
    int bh = (g >> 16) & 31;
    int tv = g >> 21;                // 0 = K, 1 = V
    const float* src = (tv ? V : K) + (((size_t)bh * SKn + r) * Dn + c4 * 4);
    float4 f = *reinterpret_cast<const float4*>(src);
    uint32_t bx = __float_as_uint(f.x), by = __float_as_uint(f.y);
    uint32_t bz = __float_as_uint(f.z), bw = __float_as_uint(f.w);
    uint2 hi = make_uint2(prmt_hi(bx, by), prmt_hi(bz, bw));
    uint2 lo = make_uint2(packbf(f.x - truncbf(f.x), f.y - truncbf(f.y)),
                          packbf(f.z - truncbf(f.z), f.w - truncbf(f.w)));
    char* base = g_scratch
        + (((size_t)bh * NCHUNK + (r >> 6)) * 4 + (tv ? 2 : 0)) * (size_t)BUF_B
        + (r & 63) * STRIDE_B + c4 * 8;
    *reinterpret_cast<uint2*>(base)         = hi;
    *reinterpret_cast<uint2*>(base + BUF_B) = lo;
}

// ---------------- main kernel ----------------
__global__ __launch_bounds__(256, 1) void attn_kernel(
    const float* __restrict__ Q, const int* __restrict__ M, float* __restrict__ O)
{
    extern __shared__ uint32_t smem[];
    uint32_t* Qh = smem;
    uint32_t* Ql = Qh + QTILE_B / 4;

    const uint32_t sbq = (uint32_t)__cvta_generic_to_shared(smem);
    const uint32_t sQh = sbq;
    const uint32_t sQl = sQh + QTILE_B;
    const uint32_t sStage = sbq + SM_STAGE0;

    const int tid  = threadIdx.x;
    const int warp = tid >> 5, lane = tid & 31;
    const int gid  = lane >> 2, qid = lane & 3;
    const int qr   = warp * 16;

    const int bh = blockIdx.y;
    const int qt = blockIdx.x;

    const float* Qg = Q + ((size_t)bh * SQn + (size_t)qt * 128) * Dn;
    const int*   Mg = M + ((size_t)bh * SQn + (size_t)qt * 128) * SKn;
    float*       Og = O + ((size_t)bh * SQn + (size_t)qt * 128) * Dn;
    const char*  Sg = g_scratch + (size_t)bh * NCHUNK * STAGE_B;

    // lane-derived ldmatrix offsets (bytes)
    const uint32_t bkOff = ((lane & 7) + ((lane >> 4) & 1) * 8) * STRIDE_B + ((lane >> 3) & 1) * 16;
    const uint32_t vOff  = ((lane & 7) + ((lane >> 3) & 1) * 8) * STRIDE_B + ((lane >> 4) & 1) * 16;
    const uint32_t qOff  = (qr + (lane & 15)) * STRIDE_B + ((lane >> 4) & 1) * 16;

    // per-thread cp.async offsets: 16 chunks of 16B each, offset within stage
    uint32_t cpoff[16];
    #pragma unroll
    for (int i = 0; i < 16; ++i) {
        int g = i * 256 + tid;              // 0..4095
        int buf = g >> 10, idx = g & 1023;
        int row = idx >> 4, col = idx & 15;
        cpoff[i] = buf * BUF_B + row * STRIDE_B + col * 16;
    }

    // ---- issue chunk 0 loads immediately ----
    {
        const char* gb = Sg;  // chunk 0
        #pragma unroll
        for (int i = 0; i < 16; ++i) cp16(sStage + cpoff[i], gb + cpoff[i]);
        CP_COMMIT();
    }

    // ---- Q tile: global -> smem (hi/lo) ----
    {
        const float4* src = reinterpret_cast<const float4*>(Qg);
        #pragma unroll
        for (int it = 0; it < 16; ++it) {
            int idx = tid + it * 256;
            int row = idx >> 5, c4 = idx & 31;
            float4 v = src[idx];
            uint32_t bx = __float_as_uint(v.x), by = __float_as_uint(v.y);
            uint32_t bz = __float_as_uint(v.z), bw = __float_as_uint(v.w);
            int off = row * STRIDE_W + c4 * 2;
            *reinterpret_cast<uint2*>(Qh + off) = make_uint2(prmt_hi(bx, by), prmt_hi(bz, bw));
            *reinterpret_cast<uint2*>(Ql + off) =
                make_uint2(packbf(v.x - truncbf(v.x), v.y - truncbf(v.y)),
                           packbf(v.z - truncbf(v.z), v.w - truncbf(v.w)));
        }
    }
    __syncthreads();

    // ---- hoist Q fragments (invariant across chunks) ----
    uint32_t qfh[8][4], qfl[8][4];
    #pragma unroll
    for (int ds = 0; ds < 8; ++ds) {
        ldsm4(qfh[ds], sQh + qOff + ds * 32);
        ldsm4(qfl[ds], sQl + qOff + ds * 32);
    }

    float o[16][4];
    #pragma unroll
    for (int i = 0; i < 16; ++i)
        #pragma unroll
        for (int j = 0; j < 4; ++j) o[i][j] = 0.f;

    #pragma unroll 1
    for (int c = 0; c < NCHUNK; ++c) {
        const uint32_t st = sStage + (c & 1) * STAGE_B;

        // issue next chunk into the other stage, then wait for current
        if (c + 1 < NCHUNK) {
            const char* gb = Sg + (size_t)(c + 1) * STAGE_B;
            const uint32_t sn = sStage + ((c + 1) & 1) * STAGE_B;
            #pragma unroll
            for (int i = 0; i < 16; ++i) cp16(sn + cpoff[i], gb + cpoff[i]);
            CP_COMMIT();
            CP_WAIT(1);
        } else {
            CP_WAIT(0);
        }
        __syncthreads();

        const uint32_t sKH = st, sKL = st + BUF_B, sVH = st + 2 * BUF_B, sVL = st + 3 * BUF_B;
        const int koff = c * CHUNK_ROWS;

        #pragma unroll 1
        for (int nc = 0; nc < 2; ++nc) {
            const int kb = nc * 32;

            // mask prefetch
            const int* m0 = Mg + (size_t)(qr + gid) * SKn + koff + kb + qid * 2;
            const int* m1 = m0 + 8 * (size_t)SKn;
            int2 ma[4], mb[4];
            #pragma unroll
            for (int j = 0; j < 4; ++j) {
                ma[j] = *reinterpret_cast<const int2*>(m0 + j * 8);
                mb[j] = *reinterpret_cast<const int2*>(m1 + j * 8);
            }

            // ---- GEMM1: S[16q x 32k] = Q·K^T (bf16x3) ----
            float s[4][4];
            #pragma unroll
            for (int j = 0; j < 4; ++j) { s[j][0]=0.f; s[j][1]=0.f; s[j][2]=0.f; s[j][3]=0.f; }

            #pragma unroll
            for (int ds = 0; ds < 8; ++ds) {
                uint32_t bh0[4], bh1[4], bl0[4], bl1[4];
                const uint32_t kcol = bkOff + ds * 32;
                ldsm4(bh0, sKH + (uint32_t)(kb     ) * STRIDE_B + kcol);
                ldsm4(bh1, sKH + (uint32_t)(kb + 16) * STRIDE_B + kcol);
                ldsm4(bl0, sKL + (uint32_t)(kb     ) * STRIDE_B + kcol);
                ldsm4(bl1, sKL + (uint32_t)(kb + 16) * STRIDE_B + kcol);
                mma16816(s[0], qfh[ds], bh0[0], bh0[1]);
                mma16816(s[1], qfh[ds], bh0[2], bh0[3]);
                mma16816(s[2], qfh[ds], bh1[0], bh1[1]);
                mma16816(s[3], qfh[ds], bh1[2], bh1[3]);
                mma16816(s[0], qfl[ds], bh0[0], bh0[1]);
                mma16816(s[1], qfl[ds], bh0[2], bh0[3]);
                mma16816(s[2], qfl[ds], bh1[0], bh1[1]);
                mma16816(s[3], qfl[ds], bh1[2], bh1[3]);
                mma16816(s[0], qfh[ds], bl0[0], bl0[1]);
                mma16816(s[1], qfh[ds], bl0[2], bl0[3]);
                mma16816(s[2], qfh[ds], bl1[0], bl1[1]);
                mma16816(s[3], qfh[ds], bl1[2], bl1[3]);
            }

            // ---- mask + scale -> P ----
            float p[4][4];
            #pragma unroll
            for (int j = 0; j < 4; ++j) {
                p[j][0] = ma[j].x ? s[j][0] * SCALE : 0.f;
                p[j][1] = ma[j].y ? s[j][1] * SCALE : 0.f;
                p[j][2] = mb[j].x ? s[j][2] * SCALE : 0.f;
                p[j][3] = mb[j].y ? s[j][3] * SCALE : 0.f;
            }

            // ---- GEMM2: O += P[16x32]·V[32x128] ----
            #pragma unroll
            for (int kk = 0; kk < 2; ++kk) {
                uint32_t ahi[4], alo[4];
                {
                    const float* p0 = p[kk*2 + 0];
                    const float* p1 = p[kk*2 + 1];
                    ahi[0] = prmt_hi(__float_as_uint(p0[0]), __float_as_uint(p0[1]));
                    ahi[1] = prmt_hi(__float_as_uint(p0[2]), __float_as_uint(p0[3]));
                    ahi[2] = prmt_hi(__float_as_uint(p1[0]), __float_as_uint(p1[1]));
                    ahi[3] = prmt_hi(__float_as_uint(p1[2]), __float_as_uint(p1[3]));
                    alo[0] = packbf(p0[0] - truncbf(p0[0]), p0[1] - truncbf(p0[1]));
                    alo[1] = packbf(p0[2] - truncbf(p0[2]), p0[3] - truncbf(p0[3]));
                    alo[2] = packbf(p1[0] - truncbf(p1[0]), p1[1] - truncbf(p1[1]));
                    alo[3] = packbf(p1[2] - truncbf(p1[2]), p1[3] - truncbf(p1[3]));
                }
                const uint32_t vbase = (uint32_t)(kb + kk * 16) * STRIDE_B + vOff;
                #pragma unroll
                for (int t = 0; t < 8; ++t) {
                    uint32_t vh[4], vl[4];
                    ldsm4t(vh, sVH + vbase + t * 32);
                    ldsm4t(vl, sVL + vbase + t * 32);
                    mma16816(o[2*t    ], ahi, vh[0], vh[1]);
                    mma16816(o[2*t + 1], ahi, vh[2], vh[3]);
                    mma16816(o[2*t    ], alo, vh[0], vh[1]);
                    mma16816(o[2*t + 1], alo, vh[2], vh[3]);
                    mma16816(o[2*t    ], ahi, vl[0], vl[1]);
                    mma16816(o[2*t + 1], ahi, vl[2], vl[3]);
                }
            }
        }
        __syncthreads();  // compute done before next issue overwrites this stage
    }

    // ---- epilogue ----
    float* o0 = Og + (size_t)(qr + gid) * Dn + qid * 2;
    float* o1 = o0 + 8 * Dn;
    #pragma unroll
    for (int nd = 0; nd < 16; ++nd) {
        *reinterpret_cast<float2*>(o0 + nd * 8) = make_float2(o[nd][0], o[nd][1]);
        *reinterpret_cast<float2*>(o1 + nd * 8) = make_float2(o[nd][2], o[nd][3]);
    }
}

} // namespace

extern "C" void kernel_launch(void* const* d_in, const int* in_sizes, int n_in,
                              void* d_out, int out_size) {
    (void)in_sizes; (void)n_in; (void)out_size;
    const float* Q = (const float*)d_in[0];
    const float* K = (const float*)d_in[1];
    const float* V = (const float*)d_in[2];
    const int*   M = (const int*)d_in[3];
    float*       O = (float*)d_out;

    prepass<<<16384, 256>>>(K, V);

    cudaFuncSetAttribute(attn_kernel, cudaFuncAttributeMaxDynamicSharedMemorySize, SMEM_TOTAL);
    dim3 grid(SQn / 128, 32);
    attn_kernel<<<grid, 256, SMEM_TOTAL>>>(Q, M, O);
}